// round 7
// baseline (speedup 1.0000x reference)
#include <cuda_runtime.h>

// Scratch: one partial per block + a completion counter.
// __device__ globals, zero-initialized — no allocation, graph-capture safe.
#define NBLOCKS 1184
__device__ float g_partials[NBLOCKS];
__device__ unsigned int g_count = 0;   // atomicInc wraps back to 0 -> deterministic across replays

__global__ void __launch_bounds__(256)
cosdist_fused_kernel(const float4* __restrict__ a,
                     const float4* __restrict__ b,
                     long long n4,
                     float* __restrict__ out,
                     float invN)
{
    float acc = 0.0f;
    long long i      = (long long)blockIdx.x * blockDim.x + threadIdx.x;
    long long stride = (long long)gridDim.x * blockDim.x;

    // 4-way unrolled grid-stride loop: 8 outstanding LDG.128 per iteration.
    for (; i + 3 * stride < n4; i += 4 * stride) {
        float4 x0 = a[i];
        float4 y0 = b[i];
        float4 x1 = a[i + stride];
        float4 y1 = b[i + stride];
        float4 x2 = a[i + 2 * stride];
        float4 y2 = b[i + 2 * stride];
        float4 x3 = a[i + 3 * stride];
        float4 y3 = b[i + 3 * stride];
        acc = fmaf(x0.x, y0.x, acc);
        acc = fmaf(x0.y, y0.y, acc);
        acc = fmaf(x0.z, y0.z, acc);
        acc = fmaf(x0.w, y0.w, acc);
        acc = fmaf(x1.x, y1.x, acc);
        acc = fmaf(x1.y, y1.y, acc);
        acc = fmaf(x1.z, y1.z, acc);
        acc = fmaf(x1.w, y1.w, acc);
        acc = fmaf(x2.x, y2.x, acc);
        acc = fmaf(x2.y, y2.y, acc);
        acc = fmaf(x2.z, y2.z, acc);
        acc = fmaf(x2.w, y2.w, acc);
        acc = fmaf(x3.x, y3.x, acc);
        acc = fmaf(x3.y, y3.y, acc);
        acc = fmaf(x3.z, y3.z, acc);
        acc = fmaf(x3.w, y3.w, acc);
    }
    // Tail: at most 3 more strided elements per thread.
    for (; i < n4; i += stride) {
        float4 x = a[i];
        float4 y = b[i];
        acc = fmaf(x.x, y.x, acc);
        acc = fmaf(x.y, y.y, acc);
        acc = fmaf(x.z, y.z, acc);
        acc = fmaf(x.w, y.w, acc);
    }

    // ---- block reduce ----
    #pragma unroll
    for (int off = 16; off > 0; off >>= 1)
        acc += __shfl_down_sync(0xFFFFFFFF, acc, off);

    __shared__ float s_warp[8];  // 256 threads = 8 warps
    int lane = threadIdx.x & 31;
    int wid  = threadIdx.x >> 5;
    if (lane == 0) s_warp[wid] = acc;
    __syncthreads();

    __shared__ bool s_is_last;
    if (threadIdx.x == 0) {
        float v = s_warp[0] + s_warp[1] + s_warp[2] + s_warp[3]
                + s_warp[4] + s_warp[5] + s_warp[6] + s_warp[7];
        g_partials[blockIdx.x] = v;
        // Make the partial visible before signalling completion.
        __threadfence();
        // atomicInc with modulus gridDim.x-1 wraps to 0 on the last block:
        // counter self-resets every launch -> deterministic graph replays.
        unsigned int prev = atomicInc(&g_count, gridDim.x - 1);
        s_is_last = (prev == gridDim.x - 1);
    }
    __syncthreads();

    // ---- last block finalizes ----
    if (s_is_last) {
        float v = 0.0f;
        for (int j = threadIdx.x; j < NBLOCKS; j += 256)
            v += g_partials[j];

        #pragma unroll
        for (int off = 16; off > 0; off >>= 1)
            v += __shfl_down_sync(0xFFFFFFFF, v, off);

        if (lane == 0) s_warp[wid] = v;
        __syncthreads();

        if (threadIdx.x == 0) {
            float total = s_warp[0] + s_warp[1] + s_warp[2] + s_warp[3]
                        + s_warp[4] + s_warp[5] + s_warp[6] + s_warp[7];
            out[0] = 1.0f - total * invN;
        }
    }
}

extern "C" void kernel_launch(void* const* d_in, const int* in_sizes, int n_in,
                              void* d_out, int out_size)
{
    const float* feats  = (const float*)d_in[0];   // [D=512, N=65536] fp32
    const float* warped = (const float*)d_in[1];   // [D=512, N=65536] fp32
    float* out = (float*)d_out;                    // scalar fp32

    long long total = (long long)in_sizes[0];      // 33,554,432 elements
    long long n4    = total >> 2;                  // 8,388,608 float4 pairs

    // N = 65536 columns; mean over N of (1 - diag[n]) = 1 - total_dot / N
    const float invN = 1.0f / 65536.0f;

    cosdist_fused_kernel<<<NBLOCKS, 256>>>(
        (const float4*)feats, (const float4*)warped, n4, out, invN);
}